// round 1
// baseline (speedup 1.0000x reference)
#include <cuda_runtime.h>

#define ROWS 8
#define NTHREADS 256

__global__ __launch_bounds__(NTHREADS)
void matcher_cost_kernel(const float* __restrict__ logits,   // [BN, C]
                         const float* __restrict__ pboxes,   // [BN, 4] cxcywh
                         const int*   __restrict__ tlabw,    // T labels (int32 or int64 words)
                         const float* __restrict__ tboxes,   // [T, 4] raw (used as-is)
                         float* __restrict__ out,            // [BN, T]
                         int BN, int C, int T)
{
    extern __shared__ char smem_raw[];
    float4* stbox = (float4*)smem_raw;                 // T target boxes (raw)
    int nlab4 = (T + 3) >> 2;
    int*   slab  = (int*)(smem_raw + (size_t)16 * T);  // packed labels, 4 per int
    float* sprob = (float*)(slab + nlab4);             // ROWS * C softmax probs
    float* srow  = sprob + ROWS * C;                   // ROWS * 9 per-row constants

    const int tid  = threadIdx.x;
    const int row0 = blockIdx.x * ROWS;

    // ---- detect int64 vs int32 label storage (JAX may silently downcast) ----
    // int64 little-endian: every odd 32-bit word of the first 8 labels is 0.
    bool is64 = (tlabw[1] == 0) & (tlabw[3] == 0) & (tlabw[5] == 0) & (tlabw[7] == 0) &
                (tlabw[9] == 0) & (tlabw[11] == 0) & (tlabw[13] == 0) & (tlabw[15] == 0);

    // ---- stage target boxes into smem (float4 each) ----
    const float4* tb4 = (const float4*)tboxes;
    for (int t = tid; t < T; t += NTHREADS)
        stbox[t] = tb4[t];

    // ---- pack labels: 4 labels per int (C = 92 < 256) ----
    for (int g = tid; g < nlab4; g += NTHREADS) {
        int packed = 0;
#pragma unroll
        for (int j = 0; j < 4; ++j) {
            int t = 4 * g + j;
            if (t < T) {
                int lab = is64 ? tlabw[2 * t] : tlabw[t];
                packed |= (lab & 0xFF) << (8 * j);
            }
        }
        slab[g] = packed;
    }

    // ---- per-row prediction box constants ----
    if (tid < ROWS) {
        int row = row0 + tid;
        if (row < BN) {
            float4 b = ((const float4*)pboxes)[row];
            float px0 = b.x - 0.5f * b.z, py0 = b.y - 0.5f * b.w;
            float px1 = b.x + 0.5f * b.z, py1 = b.y + 0.5f * b.w;
            float* rc = srow + tid * 9;
            rc[0] = b.x; rc[1] = b.y; rc[2] = b.z; rc[3] = b.w;
            rc[4] = px0; rc[5] = py0; rc[6] = px1; rc[7] = py1;
            rc[8] = (px1 - px0) * (py1 - py0);   // area from converted coords (match ref)
        }
    }

    // ---- softmax: one warp per row (C = 92, 3 strided passes) ----
    {
        int warp = tid >> 5, lane = tid & 31;
        int row = row0 + warp;
        if (row < BN) {
            const float* lg = logits + (size_t)row * C;
            float m = -3.4e38f;
            for (int c = lane; c < C; c += 32) m = fmaxf(m, __ldg(lg + c));
#pragma unroll
            for (int o = 16; o; o >>= 1) m = fmaxf(m, __shfl_xor_sync(0xFFFFFFFFu, m, o));
            float s = 0.f;
            float* pr = sprob + warp * C;
            for (int c = lane; c < C; c += 32) {
                float e = __expf(__ldg(lg + c) - m);
                s += e;
                pr[c] = e;
            }
#pragma unroll
            for (int o = 16; o; o >>= 1) s += __shfl_xor_sync(0xFFFFFFFFu, s, o);
            float inv = 1.0f / s;
            for (int c = lane; c < C; c += 32) pr[c] *= inv;
        }
    }
    __syncthreads();

    const bool vec = ((T & 3) == 0);
    const int nT4 = T >> 2;

    // ---- main: each thread emits 4 consecutive targets (one STG.128) ----
    for (int r = 0; r < ROWS; ++r) {
        int row = row0 + r;
        if (row >= BN) break;
        const float* rc = srow + r * 9;
        const float cx  = rc[0], cy  = rc[1], pw  = rc[2], ph  = rc[3];
        const float px0 = rc[4], py0 = rc[5], px1 = rc[6], py1 = rc[7];
        const float pa  = rc[8];
        const float* pr = sprob + r * C;
        float* orow = out + (size_t)row * T;

        if (vec) {
            float4* orow4 = (float4*)orow;
            for (int i = tid; i < nT4; i += NTHREADS) {
                int packed = slab[i];
                float4 res;
#pragma unroll
                for (int j = 0; j < 4; ++j) {
                    float4 tb = stbox[4 * i + j];
                    int lab = (packed >> (8 * j)) & 0xFF;
                    float p = pr[lab];
                    // L1 on raw cxcywh vs raw target
                    float l1 = fabsf(cx - tb.x) + fabsf(cy - tb.y)
                             + fabsf(pw - tb.z) + fabsf(ph - tb.w);
                    // GIoU: pred xyxy vs target used as-is
                    float a2 = (tb.z - tb.x) * (tb.w - tb.y);
                    float iw = fmaxf(fminf(px1, tb.z) - fmaxf(px0, tb.x), 0.f);
                    float ih = fmaxf(fminf(py1, tb.w) - fmaxf(py0, tb.y), 0.f);
                    float inter = iw * ih;
                    float uni = pa + a2 - inter;
                    float ew = fmaxf(fmaxf(px1, tb.z) - fminf(px0, tb.x), 0.f);
                    float eh = fmaxf(fmaxf(py1, tb.w) - fminf(py0, tb.y), 0.f);
                    float ae = ew * eh;
                    // giou = inter/uni - (ae-uni)/ae == (inter*ae + uni*uni)/(uni*ae) - 1
                    float giou = (inter * ae + uni * uni) / (uni * ae) - 1.0f;
                    float c = (1.0f - p) + 5.0f * l1 + 2.0f * (1.0f - giou);
                    (&res.x)[j] = c;
                }
                orow4[i] = res;
            }
        } else {
            for (int t = tid; t < T; t += NTHREADS) {
                float4 tb = stbox[t];
                int lab = (slab[t >> 2] >> (8 * (t & 3))) & 0xFF;
                float p = pr[lab];
                float l1 = fabsf(cx - tb.x) + fabsf(cy - tb.y)
                         + fabsf(pw - tb.z) + fabsf(ph - tb.w);
                float a2 = (tb.z - tb.x) * (tb.w - tb.y);
                float iw = fmaxf(fminf(px1, tb.z) - fmaxf(px0, tb.x), 0.f);
                float ih = fmaxf(fminf(py1, tb.w) - fmaxf(py0, tb.y), 0.f);
                float inter = iw * ih;
                float uni = pa + a2 - inter;
                float ew = fmaxf(fmaxf(px1, tb.z) - fminf(px0, tb.x), 0.f);
                float eh = fmaxf(fmaxf(py1, tb.w) - fminf(py0, tb.y), 0.f);
                float ae = ew * eh;
                float giou = (inter * ae + uni * uni) / (uni * ae) - 1.0f;
                orow[t] = (1.0f - p) + 5.0f * l1 + 2.0f * (1.0f - giou);
            }
        }
    }
}

extern "C" void kernel_launch(void* const* d_in, const int* in_sizes, int n_in,
                              void* d_out, int out_size)
{
    const float* logits = (const float*)d_in[0];   // out_labels [B,N,C]
    const float* pboxes = (const float*)d_in[1];   // out_bboxes [B,N,4]
    const int*   tlabw  = (const int*)d_in[2];     // tgt_labels [T] (int32 or int64)
    const float* tboxes = (const float*)d_in[3];   // tgt_bboxes [T,4]
    float* out = (float*)d_out;

    int BN = in_sizes[1] / 4;
    int C  = in_sizes[0] / BN;
    int T  = in_sizes[2];
    int nlab4 = (T + 3) / 4;

    size_t smem = (size_t)16 * T + 4 * (size_t)nlab4
                + 4 * (size_t)ROWS * C + 4 * (size_t)ROWS * 9 + 16;

    int grid = (BN + ROWS - 1) / ROWS;
    matcher_cost_kernel<<<grid, NTHREADS, smem>>>(logits, pboxes, tlabw, tboxes,
                                                  out, BN, C, T);
}

// round 2
// speedup vs baseline: 1.4006x; 1.4006x over previous
#include <cuda_runtime.h>

#define ROWS 16
#define NTHREADS 256

__global__ __launch_bounds__(NTHREADS, 4)
void matcher_cost_kernel2(const float* __restrict__ logits,   // [BN, C]
                          const float* __restrict__ pboxes,   // [BN, 4] cxcywh
                          const int*   __restrict__ tlabw,    // T labels (int32 or int64 words)
                          const float* __restrict__ tboxes,   // [T, 4] raw (used as-is)
                          float* __restrict__ out,            // [BN, T]
                          int BN, int C, int T)
{
    extern __shared__ float sm[];
    float*  sprob = sm;                                   // ROWS * C  (stores 5 - p)
    int prob_off = (ROWS * C + 3) & ~3;                   // 16B align
    float4* srow  = (float4*)(sm + prob_off);             // ROWS * 3 float4

    const int tid  = threadIdx.x;
    const int row0 = blockIdx.x * ROWS;

    // ---- detect int64 vs int32 label storage (odd 32-bit words all zero) ----
    bool is64 = false;
    if (T >= 8) {
        is64 = (tlabw[1] == 0) & (tlabw[3] == 0) & (tlabw[5] == 0) & (tlabw[7] == 0) &
               (tlabw[9] == 0) & (tlabw[11] == 0) & (tlabw[13] == 0) & (tlabw[15] == 0);
    }

    // ---- per-row prediction-box constants (12 floats each, 3 float4) ----
    if (tid < ROWS) {
        int row = row0 + tid;
        if (row < BN) {
            float4 b = ((const float4*)pboxes)[row];
            float px0 = b.x - 0.5f * b.z, py0 = b.y - 0.5f * b.w;
            float px1 = b.x + 0.5f * b.z, py1 = b.y + 0.5f * b.w;
            srow[tid * 3 + 0] = b;                                  // cx cy pw ph
            srow[tid * 3 + 1] = make_float4(px0, py0, px1, py1);
            srow[tid * 3 + 2] = make_float4((px1 - px0) * (py1 - py0), 0.f, 0.f, 0.f);
        }
    }

    // ---- softmax (one warp per row, strided); store 5 - p ----
    {
        int warp = tid >> 5, lane = tid & 31;
        for (int lr = warp; lr < ROWS; lr += NTHREADS / 32) {
            int row = row0 + lr;
            if (row >= BN) continue;
            const float* lg = logits + (size_t)row * C;
            float m = -3.4e38f;
            for (int c = lane; c < C; c += 32) m = fmaxf(m, __ldg(lg + c));
#pragma unroll
            for (int o = 16; o; o >>= 1) m = fmaxf(m, __shfl_xor_sync(0xFFFFFFFFu, m, o));
            float s = 0.f;
            float* pr = sprob + lr * C;
            for (int c = lane; c < C; c += 32) {
                float e = __expf(__ldg(lg + c) - m);
                s += e;
                pr[c] = e;
            }
#pragma unroll
            for (int o = 16; o; o >>= 1) s += __shfl_xor_sync(0xFFFFFFFFu, s, o);
            float ninv = -1.0f / s;
            for (int c = lane; c < C; c += 32) pr[c] = fmaf(pr[c], ninv, 5.0f);
        }
    }
    __syncthreads();

    const int rows_here = min(ROWS, BN - row0);
    const float4* tb4 = (const float4*)tboxes;

    // ---- each thread owns 4 targets in registers, loops over rows ----
    for (int tb0 = 4 * tid; tb0 < T; tb0 += 4 * NTHREADS) {
        int nv = min(4, T - tb0);
        bool full = (nv == 4);

        float4 t[4];
        float  a2[4];
        int    lb[4];
#pragma unroll
        for (int j = 0; j < 4; ++j) {
            if (j < nv) {
                t[j]  = tb4[tb0 + j];
                lb[j] = is64 ? tlabw[2 * (tb0 + j)] : tlabw[tb0 + j];
                a2[j] = (t[j].z - t[j].x) * (t[j].w - t[j].y);
            } else {
                t[j] = make_float4(0.f, 0.f, 1.f, 1.f);
                lb[j] = 0;
                a2[j] = 1.f;
            }
        }

        float* optr = out + (size_t)row0 * T + tb0;
        const float* pr = sprob;
        for (int r = 0; r < rows_here; ++r, optr += T, pr += C) {
            float4 c0 = srow[r * 3 + 0];     // cx cy pw ph
            float4 c1 = srow[r * 3 + 1];     // px0 py0 px1 py1
            float  pa = srow[r * 3 + 2].x;

            float4 res;
#pragma unroll
            for (int j = 0; j < 4; ++j) {
                float tx = t[j].x, ty = t[j].y, tz = t[j].z, tw = t[j].w;
                float base = pr[lb[j]];                          // 5 - p
                float l1 = fabsf(c0.x - tx) + fabsf(c0.y - ty)
                         + fabsf(c0.z - tz) + fabsf(c0.w - tw);
                float iw = fminf(c1.z, tz) - fmaxf(c1.x, tx);
                float ih = fminf(c1.w, tw) - fmaxf(c1.y, ty);
                float inter = fmaxf(iw, 0.f) * fmaxf(ih, 0.f);
                float uni = pa + a2[j] - inter;
                float ew = fmaxf(c1.z, tz) - fminf(c1.x, tx);    // >= 0 always
                float eh = fmaxf(c1.w, tw) - fminf(c1.y, ty);    // >= 0 always
                float ae = ew * eh;
                float q  = __fdividef(fmaf(uni, uni, inter * ae), uni * ae);
                (&res.x)[j] = fmaf(-2.f, q, fmaf(5.f, l1, base));
            }
            if (full) {
                *(float4*)optr = res;
            } else {
#pragma unroll
                for (int j = 0; j < 4; ++j)
                    if (j < nv) optr[j] = (&res.x)[j];
            }
        }
    }
}

extern "C" void kernel_launch(void* const* d_in, const int* in_sizes, int n_in,
                              void* d_out, int out_size)
{
    const float* logits = (const float*)d_in[0];   // out_labels [B,N,C]
    const float* pboxes = (const float*)d_in[1];   // out_bboxes [B,N,4]
    const int*   tlabw  = (const int*)d_in[2];     // tgt_labels [T] (int32 or int64)
    const float* tboxes = (const float*)d_in[3];   // tgt_bboxes [T,4]
    float* out = (float*)d_out;

    int BN = in_sizes[1] / 4;
    int C  = in_sizes[0] / BN;
    int T  = in_sizes[2];

    int prob_off = (ROWS * C + 3) & ~3;
    size_t smem = (size_t)(prob_off + ROWS * 12) * sizeof(float) + 16;

    int grid = (BN + ROWS - 1) / ROWS;
    matcher_cost_kernel2<<<grid, NTHREADS, smem>>>(logits, pboxes, tlabw, tboxes,
                                                   out, BN, C, T);
}

// round 3
// speedup vs baseline: 1.4646x; 1.0457x over previous
#include <cuda_runtime.h>

#define ROWS 25
#define NTHREADS 256

__global__ __launch_bounds__(NTHREADS, 4)
void matcher_cost_kernel3(const float* __restrict__ logits,   // [BN, C]
                          const float* __restrict__ pboxes,   // [BN, 4] cxcywh
                          const int*   __restrict__ tlabw,    // T labels (int32 or int64 words)
                          const float* __restrict__ tboxes,   // [T, 4] raw (used as-is)
                          float* __restrict__ out,            // [BN, T]
                          int BN, int C, int T)
{
    extern __shared__ float sm[];
    float*  sprob = sm;                                   // ROWS * C  (stores 5 - p)
    int prob_off = (ROWS * C + 3) & ~3;                   // 16B align
    float4* srow  = (float4*)(sm + prob_off);             // ROWS * 3 float4

    const int tid  = threadIdx.x;
    const int row0 = blockIdx.x * ROWS;

    // ---- detect int64 vs int32 label storage (odd 32-bit words all zero) ----
    bool is64 = false;
    if (T >= 8) {
        is64 = (tlabw[1] == 0) & (tlabw[3] == 0) & (tlabw[5] == 0) & (tlabw[7] == 0) &
               (tlabw[9] == 0) & (tlabw[11] == 0) & (tlabw[13] == 0) & (tlabw[15] == 0);
    }

    // ---- per-row prediction-box constants (12 floats each, 3 float4) ----
    if (tid < ROWS) {
        int row = row0 + tid;
        if (row < BN) {
            float4 b = ((const float4*)pboxes)[row];
            float px0 = b.x - 0.5f * b.z, py0 = b.y - 0.5f * b.w;
            float px1 = b.x + 0.5f * b.z, py1 = b.y + 0.5f * b.w;
            srow[tid * 3 + 0] = b;                                  // cx cy pw ph
            srow[tid * 3 + 1] = make_float4(px0, py0, px1, py1);
            srow[tid * 3 + 2] = make_float4((px1 - px0) * (py1 - py0), 0.f, 0.f, 0.f);
        }
    }

    // ---- softmax (one warp per row, strided); store 5 - p ----
    {
        int warp = tid >> 5, lane = tid & 31;
        for (int lr = warp; lr < ROWS; lr += NTHREADS / 32) {
            int row = row0 + lr;
            if (row >= BN) continue;
            const float* lg = logits + (size_t)row * C;
            float m = -3.4e38f;
            for (int c = lane; c < C; c += 32) m = fmaxf(m, __ldg(lg + c));
#pragma unroll
            for (int o = 16; o; o >>= 1) m = fmaxf(m, __shfl_xor_sync(0xFFFFFFFFu, m, o));
            float s = 0.f;
            float* pr = sprob + lr * C;
            for (int c = lane; c < C; c += 32) {
                float e = __expf(__ldg(lg + c) - m);
                s += e;
                pr[c] = e;
            }
#pragma unroll
            for (int o = 16; o; o >>= 1) s += __shfl_xor_sync(0xFFFFFFFFu, s, o);
            float ninv = -1.0f / s;
            for (int c = lane; c < C; c += 32) pr[c] = fmaf(pr[c], ninv, 5.0f);
        }
    }
    __syncthreads();

    const int rows_here = min(ROWS, BN - row0);
    const float4* tb4 = (const float4*)tboxes;

    // ---- each thread owns 4 targets in registers, loops over rows ----
    for (int tb0 = 4 * tid; tb0 < T; tb0 += 4 * NTHREADS) {
        int nv = min(4, T - tb0);
        bool full = (nv == 4);

        float4 t[4];
        float  twd[4], thd[4];
        int    lb[4];
#pragma unroll
        for (int j = 0; j < 4; ++j) {
            if (j < nv) {
                t[j]  = tb4[tb0 + j];
                lb[j] = is64 ? tlabw[2 * (tb0 + j)] : tlabw[tb0 + j];
            } else {
                t[j]  = make_float4(0.f, 0.f, 1.f, 1.f);
                lb[j] = 0;
            }
            twd[j] = t[j].z - t[j].x;   // target "width"  (xyxy interp)
            thd[j] = t[j].w - t[j].y;   // target "height"
        }

        float* optr = out + (size_t)row0 * T + tb0;
        const float* pr = sprob;
        for (int r = 0; r < rows_here; ++r, optr += T, pr += C) {
            float4 c0 = srow[r * 3 + 0];     // cx cy pw ph
            float4 c1 = srow[r * 3 + 1];     // px0 py0 px1 py1
            float  pa = srow[r * 3 + 2].x;

            float4 res;
#pragma unroll
            for (int j = 0; j < 4; ++j) {
                float tx = t[j].x, ty = t[j].y, tz = t[j].z, tw = t[j].w;
                float base = pr[lb[j]];                          // 5 - p
                float l1 = fabsf(c0.x - tx) + fabsf(c0.y - ty)
                         + fabsf(c0.z - tz) + fabsf(c0.w - tw);
                float iw = fminf(c1.z, tz) - fmaxf(c1.x, tx);
                float ih = fminf(c1.w, tw) - fmaxf(c1.y, ty);
                float inter = fmaxf(iw, 0.f) * fmaxf(ih, 0.f);
                // enclosing box via min+max = a+b identity:
                float ew = (c0.z + twd[j]) - iw;                 // pw + twd - iw
                float eh = (c0.w + thd[j]) - ih;                 // ph + thd - ih
                float ae = ew * eh;
                float uni = fmaf(twd[j], thd[j], pa) - inter;    // pa + a2 - inter
                float q  = __fdividef(fmaf(uni, uni, inter * ae), uni * ae);
                (&res.x)[j] = fmaf(-2.f, q, fmaf(5.f, l1, base));
            }
            if (full) {
                *(float4*)optr = res;
            } else {
#pragma unroll
                for (int j = 0; j < 4; ++j)
                    if (j < nv) optr[j] = (&res.x)[j];
            }
        }
    }
}

extern "C" void kernel_launch(void* const* d_in, const int* in_sizes, int n_in,
                              void* d_out, int out_size)
{
    const float* logits = (const float*)d_in[0];   // out_labels [B,N,C]
    const float* pboxes = (const float*)d_in[1];   // out_bboxes [B,N,4]
    const int*   tlabw  = (const int*)d_in[2];     // tgt_labels [T] (int32 or int64)
    const float* tboxes = (const float*)d_in[3];   // tgt_bboxes [T,4]
    float* out = (float*)d_out;

    int BN = in_sizes[1] / 4;
    int C  = in_sizes[0] / BN;
    int T  = in_sizes[2];

    int prob_off = (ROWS * C + 3) & ~3;
    size_t smem = (size_t)(prob_off + ROWS * 12) * sizeof(float) + 16;

    int grid = (BN + ROWS - 1) / ROWS;
    matcher_cost_kernel3<<<grid, NTHREADS, smem>>>(logits, pboxes, tlabw, tboxes,
                                                   out, BN, C, T);
}